// round 1
// baseline (speedup 1.0000x reference)
#include <cuda_runtime.h>
#include <math.h>

// ---------------- problem dims ----------------
#define BB   8
#define SS   512      // src seq len (== tgt seq len)
#define LL   6
#define HH   8
#define DD   512
#define DKK  64
#define DFF  2048
#define MS   (BB*SS)          // 4096 rows
#define HD   (HH*DKK)         // 512

// ---------------- scratch (device globals; allocation-free) ----------------
__device__ float g_x  [MS*DD];          // encoder activations / enc output
__device__ float g_y  [MS*DD];          // decoder activations
__device__ float g_qkv[MS*3*HD];        // packed QKV (or Q + KV for cross)
__device__ float g_P  [BB*HH*SS*SS];    // attention probs (64 MB)
__device__ float g_ao [MS*DD];          // attn head-concat output
__device__ float g_a  [MS*DD];          // sublayer output (pre-LN)
__device__ float g_ff [MS*DFF];         // FF hidden
__device__ float g_wp [DD*3*HD];        // repacked qkv weights
__device__ float g_bp [3*HD];           // repacked qkv bias
__device__ float g_pe [SS*DD];          // positional encoding table

// ---------------- GEMM ----------------
// C[z] = alpha * A[z] * B[z](^T) + bias ; per-batch offsets split as
// off = (z/zdiv)*s + (z%zdiv)*s2 for A, B, C.
template<int BM,int BN,int BK,int TM,int TN,bool TRANSB>
__global__ __launch_bounds__((BM/TM)*(BN/TN))
void gemm_kernel(const float* __restrict__ A, const float* __restrict__ B,
                 float* __restrict__ C, const float* __restrict__ bias,
                 int K, int lda, int ldb, int ldc,
                 long sA, long sA2, long sB, long sB2, long sC, long sC2, int zdiv,
                 float alpha, int relu)
{
    constexpr int THREADS = (BM/TM)*(BN/TN);
    __shared__ float As[BK][BM+4];
    __shared__ float Bs[BK][BN+4];

    long z  = blockIdx.z;
    long zq = z / zdiv, zr = z % zdiv;
    A += zq*sA + zr*sA2;
    B += zq*sB + zr*sB2;
    C += zq*sC + zr*sC2;

    const int bm = blockIdx.y*BM, bn = blockIdx.x*BN;
    const int tid  = threadIdx.x;
    const int tcol = tid % (BN/TN);
    const int trow = tid / (BN/TN);

    float acc[TM][TN];
    #pragma unroll
    for (int i = 0; i < TM; i++)
        #pragma unroll
        for (int j = 0; j < TN; j++) acc[i][j] = 0.f;

    for (int k0 = 0; k0 < K; k0 += BK) {
        // A tile -> As[k][m] (transposed)
        #pragma unroll
        for (int i = tid; i < BM*BK/4; i += THREADS) {
            int r  = i / (BK/4);
            int c4 = (i % (BK/4))*4;
            float4 v = *(const float4*)(A + (long)(bm+r)*lda + k0 + c4);
            As[c4+0][r] = v.x; As[c4+1][r] = v.y;
            As[c4+2][r] = v.z; As[c4+3][r] = v.w;
        }
        if (!TRANSB) {
            #pragma unroll
            for (int i = tid; i < BK*BN/4; i += THREADS) {
                int r  = i / (BN/4);
                int c4 = (i % (BN/4))*4;
                float4 v = *(const float4*)(B + (long)(k0+r)*ldb + bn + c4);
                *(float4*)&Bs[r][c4] = v;
            }
        } else {
            #pragma unroll
            for (int i = tid; i < BN*BK/4; i += THREADS) {
                int n  = i / (BK/4);
                int c4 = (i % (BK/4))*4;
                float4 v = *(const float4*)(B + (long)(bn+n)*ldb + k0 + c4);
                Bs[c4+0][n] = v.x; Bs[c4+1][n] = v.y;
                Bs[c4+2][n] = v.z; Bs[c4+3][n] = v.w;
            }
        }
        __syncthreads();

        #pragma unroll
        for (int kk = 0; kk < BK; kk++) {
            float a_frag[TM], b_frag[TN];
            #pragma unroll
            for (int i = 0; i < TM; i += 4)
                *(float4*)&a_frag[i] = *(const float4*)&As[kk][trow*TM + i];
            #pragma unroll
            for (int j = 0; j < TN; j += 4)
                *(float4*)&b_frag[j] = *(const float4*)&Bs[kk][tcol*TN + j];
            #pragma unroll
            for (int i = 0; i < TM; i++)
                #pragma unroll
                for (int j = 0; j < TN; j++)
                    acc[i][j] += a_frag[i]*b_frag[j];
        }
        __syncthreads();
    }

    #pragma unroll
    for (int i = 0; i < TM; i++) {
        long r = bm + trow*TM + i;
        #pragma unroll
        for (int j = 0; j < TN; j++) {
            int gn = bn + tcol*TN + j;
            float v = alpha*acc[i][j];
            if (bias) v += bias[gn];
            if (relu) v = fmaxf(v, 0.f);
            C[r*(long)ldc + gn] = v;
        }
    }
}

// ---------------- softmax (exp -> mask -> normalize, max-stabilized) ----------------
__global__ void softmax_kernel(float* __restrict__ P, int Sk, int causal)
{
    int q = blockIdx.x;               // gridDim.x == Sq
    long z = blockIdx.y;
    float* row = P + (z*(long)gridDim.x + q)*(long)Sk;
    int valid = causal ? (q+1) : Sk;
    int tid = threadIdx.x;

    __shared__ float red[256];
    float m = -1e30f;
    for (int i = tid; i < valid; i += 256) m = fmaxf(m, row[i]);
    red[tid] = m; __syncthreads();
    for (int s = 128; s > 0; s >>= 1) { if (tid < s) red[tid] = fmaxf(red[tid], red[tid+s]); __syncthreads(); }
    m = red[0]; __syncthreads();

    float ev[2];
    int cnt = 0;
    float sum = 0.f;
    for (int i = tid; i < Sk; i += 256) {
        float e = (i < valid) ? expf(row[i] - m) : 0.f;
        ev[cnt++] = e;
        sum += e;
    }
    red[tid] = sum; __syncthreads();
    for (int s = 128; s > 0; s >>= 1) { if (tid < s) red[tid] += red[tid+s]; __syncthreads(); }
    float inv = 1.f / red[0];
    cnt = 0;
    for (int i = tid; i < Sk; i += 256) row[i] = ev[cnt++]*inv;
}

// ---------------- residual + LayerNorm ----------------
__global__ void add_ln_kernel(const float* __restrict__ x, const float* __restrict__ a,
                              const float* __restrict__ g, const float* __restrict__ b,
                              float* __restrict__ out)
{
    long row = blockIdx.x;
    int tid = threadIdx.x;
    const float* xr = x + row*DD;
    const float* ar = a + row*DD;
    float v0 = xr[tid]      + ar[tid];
    float v1 = xr[tid+256]  + ar[tid+256];

    __shared__ float red[256];
    red[tid] = v0 + v1; __syncthreads();
    for (int s = 128; s > 0; s >>= 1) { if (tid < s) red[tid] += red[tid+s]; __syncthreads(); }
    float mean = red[0]*(1.f/DD);
    __syncthreads();
    red[tid] = v0*v0 + v1*v1; __syncthreads();
    for (int s = 128; s > 0; s >>= 1) { if (tid < s) red[tid] += red[tid+s]; __syncthreads(); }
    float var = red[0]*(1.f/DD) - mean*mean;
    float rs = rsqrtf(var + 1e-5f);
    out[row*DD + tid]     = (v0-mean)*rs*g[tid]     + b[tid];
    out[row*DD + tid+256] = (v1-mean)*rs*g[tid+256] + b[tid+256];
}

// ---------------- positional encoding ----------------
__global__ void pe_kernel(float* __restrict__ pe)
{
    int idx = blockIdx.x*blockDim.x + threadIdx.x;
    if (idx >= SS*DD) return;
    int d = idx & (DD-1);
    int s = idx >> 9;
    int i = d >> 1;
    double denom = exp(-log(10000.0) * (double)i / 256.0);
    double ang = (double)s * denom;
    pe[idx] = (d & 1) ? (float)cos(ang) : (float)sin(ang);
}

__global__ void add_pe_kernel(const float* __restrict__ src, const float* __restrict__ pe,
                              float* __restrict__ out)
{
    int idx = blockIdx.x*blockDim.x + threadIdx.x;
    if (idx >= MS*DD) return;
    out[idx] = src[idx] + pe[idx & (SS*DD - 1)];
}

// ---------------- weight repack: [P0..P0+NP)[H][D][DK] -> [D][NP*H*DK] ----------------
__global__ void repack_w_kernel(const float* __restrict__ w, float* __restrict__ wp,
                                int P0, int NP)
{
    int n = NP*HD;
    int total = DD*n;
    int idx = blockIdx.x*blockDim.x + threadIdx.x;
    if (idx >= total) return;
    int j = idx % n, d = idx / n;
    int p = j / HD, rem = j % HD;
    int h = rem / DKK, k = rem % DKK;
    wp[idx] = w[(((long)(P0+p)*HH + h)*DD + d)*DKK + k];
}
__global__ void repack_b_kernel(const float* __restrict__ b, float* __restrict__ bp,
                                int P0, int NP)
{
    int n = NP*HD;
    int idx = blockIdx.x*blockDim.x + threadIdx.x;
    if (idx >= n) return;
    int p = idx / HD, rem = idx % HD;
    bp[idx] = b[(P0+p)*HD + rem];
}

// ---------------- host orchestration ----------------
static float *px, *py, *pqkv, *pP, *pao, *pa, *pff, *pwp, *pbp, *ppe;

static void get_ptrs()
{
    if (px) return;
    cudaGetSymbolAddress((void**)&px,  g_x);
    cudaGetSymbolAddress((void**)&py,  g_y);
    cudaGetSymbolAddress((void**)&pqkv,g_qkv);
    cudaGetSymbolAddress((void**)&pP,  g_P);
    cudaGetSymbolAddress((void**)&pao, g_ao);
    cudaGetSymbolAddress((void**)&pa,  g_a);
    cudaGetSymbolAddress((void**)&pff, g_ff);
    cudaGetSymbolAddress((void**)&pwp, g_wp);
    cudaGetSymbolAddress((void**)&pbp, g_bp);
    cudaGetSymbolAddress((void**)&ppe, g_pe);
}

static void launch_gemm(bool small, bool transb,
    const float* A, const float* B, float* C, const float* bias,
    int M, int N, int K, int lda, int ldb, int ldc,
    long sA, long sA2, long sB, long sB2, long sC, long sC2, int zdiv, int batch,
    float alpha, int relu)
{
    if (small) {
        dim3 grid(N/64, M/64, batch);
        gemm_kernel<64,64,16,4,4,false><<<grid,256>>>(A,B,C,bias,K,lda,ldb,ldc,
            sA,sA2,sB,sB2,sC,sC2,zdiv,alpha,relu);
    } else if (transb) {
        dim3 grid(N/128, M/128, batch);
        gemm_kernel<128,128,8,8,8,true><<<grid,256>>>(A,B,C,bias,K,lda,ldb,ldc,
            sA,sA2,sB,sB2,sC,sC2,zdiv,alpha,relu);
    } else {
        dim3 grid(N/128, M/128, batch);
        gemm_kernel<128,128,8,8,8,false><<<grid,256>>>(A,B,C,bias,K,lda,ldb,ldc,
            sA,sA2,sB,sB2,sC,sC2,zdiv,alpha,relu);
    }
}

// full MHA sublayer: result (pre-LN) in g_a
static void attn_block(const float* xq, const float* xkv, bool cross,
                       const float* w, const float* bqkv,
                       const float* wo, const float* bo, int causal)
{
    if (!cross) {
        int n = 3*HD;
        repack_w_kernel<<<(DD*n+255)/256,256>>>(w, pwp, 0, 3);
        repack_b_kernel<<<(n+255)/256,256>>>(bqkv, pbp, 0, 3);
        launch_gemm(false,false, xq, pwp, pqkv, pbp, MS, n, DD, DD, n, n,
                    0,0,0,0,0,0,1,1, 1.f,0);
    } else {
        repack_w_kernel<<<(DD*HD+255)/256,256>>>(w, pwp, 0, 1);
        repack_b_kernel<<<(HD+255)/256,256>>>(bqkv, pbp, 0, 1);
        launch_gemm(false,false, xq, pwp, pqkv, pbp, MS, HD, DD, DD, HD, HD,
                    0,0,0,0,0,0,1,1, 1.f,0);
        repack_w_kernel<<<(DD*2*HD+255)/256,256>>>(w, pwp, 1, 2);
        repack_b_kernel<<<(2*HD+255)/256,256>>>(bqkv, pbp, 1, 2);
        launch_gemm(false,false, xkv, pwp, pqkv + (long)MS*HD, pbp, MS, 2*HD, DD,
                    DD, 2*HD, 2*HD, 0,0,0,0,0,0,1,1, 1.f,0);
    }

    const float *qb, *kb, *vb;
    int qld, kvld;
    if (!cross) { qb = pqkv; qld = 3*HD; kb = pqkv + HD; vb = pqkv + 2*HD; kvld = 3*HD; }
    else        { qb = pqkv; qld = HD;   kb = pqkv + (long)MS*HD; vb = kb + HD; kvld = 2*HD; }

    // logits[b,h,q,s] = (1/8) * Q . K^T     (batched over z = b*H + h)
    launch_gemm(false,true, qb, kb, pP, nullptr,
        SS, SS, DKK, qld, kvld, SS,
        (long)SS*qld, DKK, (long)SS*kvld, DKK,
        (long)HH*SS*SS, (long)SS*SS, HH, BB*HH,
        0.125f, 0);

    softmax_kernel<<<dim3(SS, BB*HH), 256>>>(pP, SS, causal);

    // o[b,h,q,k] = P . V  -> concat-head layout [b*S][H*DK]
    launch_gemm(true,false, pP, vb, pao, nullptr,
        SS, DKK, SS, SS, kvld, HD,
        (long)HH*SS*SS, (long)SS*SS, (long)SS*kvld, DKK,
        (long)SS*HD, DKK, HH, BB*HH,
        1.f, 0);

    // output projection
    launch_gemm(false,false, pao, wo, pa, bo, MS, DD, HD, HD, DD, DD,
                0,0,0,0,0,0,1,1, 1.f,0);
}

static void ffn_block(const float* x, const float* w1, const float* b1,
                      const float* w2, const float* b2)
{
    launch_gemm(false,false, x,   w1, pff, b1, MS, DFF, DD,  DD,  DFF, DFF,
                0,0,0,0,0,0,1,1, 1.f,1);
    launch_gemm(false,false, pff, w2, pa,  b2, MS, DD,  DFF, DFF, DD,  DD,
                0,0,0,0,0,0,1,1, 1.f,0);
}

extern "C" void kernel_launch(void* const* d_in, const int* in_sizes, int n_in,
                              void* d_out, int out_size)
{
    const float* src  = (const float*)d_in[0];
    const float* tgt  = (const float*)d_in[1];
    const float* eaw  = (const float*)d_in[2];
    const float* eab  = (const float*)d_in[3];
    const float* ewo  = (const float*)d_in[4];
    const float* ebo  = (const float*)d_in[5];
    const float* elg  = (const float*)d_in[6];
    const float* elb  = (const float*)d_in[7];
    const float* efw1 = (const float*)d_in[8];
    const float* efb1 = (const float*)d_in[9];
    const float* efw2 = (const float*)d_in[10];
    const float* efb2 = (const float*)d_in[11];
    const float* daw  = (const float*)d_in[12];
    const float* dab  = (const float*)d_in[13];
    const float* dwo  = (const float*)d_in[14];
    const float* dbo  = (const float*)d_in[15];
    const float* dlg  = (const float*)d_in[16];
    const float* dlb  = (const float*)d_in[17];
    const float* dfw1 = (const float*)d_in[18];
    const float* dfb1 = (const float*)d_in[19];
    const float* dfw2 = (const float*)d_in[20];
    const float* dfb2 = (const float*)d_in[21];
    float* out = (float*)d_out;

    get_ptrs();

    pe_kernel<<<(SS*DD+255)/256,256>>>(ppe);
    add_pe_kernel<<<(MS*DD+255)/256,256>>>(src, ppe, px);

    const long WATT = (long)3*HH*DD*DKK;   // 786432: per-(layer[,branch]) attn weight slice
    const long WO_S = (long)HD*DD;         // 262144

    // ---------------- encoder ----------------
    for (int l = 0; l < LL; l++) {
        attn_block(px, px, false,
                   eaw + (long)l*WATT, eab + (long)l*3*HD,
                   ewo + (long)l*WO_S, ebo + (long)l*DD, 0);
        add_ln_kernel<<<MS,256>>>(px, pa, elg + (long)l*2*DD,      elb + (long)l*2*DD,      px);
        ffn_block(px, efw1 + (long)l*DD*DFF, efb1 + (long)l*DFF,
                      efw2 + (long)l*DFF*DD, efb2 + (long)l*DD);
        add_ln_kernel<<<MS,256>>>(px, pa, elg + (long)l*2*DD + DD, elb + (long)l*2*DD + DD, px);
    }

    // ---------------- decoder ----------------
    add_pe_kernel<<<(MS*DD+255)/256,256>>>(tgt, ppe, py);

    for (int l = 0; l < LL; l++) {
        // masked self-attention
        attn_block(py, py, false,
                   daw + (long)(l*2+0)*WATT, dab + (long)(l*2+0)*3*HD,
                   dwo + (long)(l*2+0)*WO_S, dbo + (long)(l*2+0)*DD, 1);
        add_ln_kernel<<<MS,256>>>(py, pa, dlg + (long)l*3*DD,        dlb + (long)l*3*DD,        py);
        // cross-attention (K/V from encoder output)
        attn_block(py, px, true,
                   daw + (long)(l*2+1)*WATT, dab + (long)(l*2+1)*3*HD,
                   dwo + (long)(l*2+1)*WO_S, dbo + (long)(l*2+1)*DD, 0);
        add_ln_kernel<<<MS,256>>>(py, pa, dlg + (long)l*3*DD + DD,   dlb + (long)l*3*DD + DD,   py);
        // feed-forward
        ffn_block(py, dfw1 + (long)l*DD*DFF, dfb1 + (long)l*DFF,
                      dfw2 + (long)l*DFF*DD, dfb2 + (long)l*DD);
        float* yo = (l == LL-1) ? out : py;
        add_ln_kernel<<<MS,256>>>(py, pa, dlg + (long)l*3*DD + 2*DD, dlb + (long)l*3*DD + 2*DD, yo);
    }
}